// round 2
// baseline (speedup 1.0000x reference)
#include <cuda_runtime.h>

// Weighted 2D Kabsch/Procrustes — closed-form (no SVD needed: z-padded 2D
// covariance has zero third row/col; R = embedded 2x2 polar factor).
// Pure HBM-bound 9-way weighted reduction over 84MB of input.

constexpr int BATCH   = 1024;
constexpr int NPTS    = 4096;
constexpr int THREADS = 128;          // 128thr x 1024 CTAs -> ~5K regs/CTA,
                                      // 8+ CTAs/SM resident -> single wave
constexpr int NWARPS  = THREADS / 32;
constexpr int ITERS   = (NPTS / 2) / THREADS;   // 16 pair-iterations per thread

__global__ __launch_bounds__(THREADS)
void kabsch2d_kernel(const float4* __restrict__ src4,   // [B, N/2] (x,y,x,y)
                     const float4* __restrict__ tgt4,
                     const float2* __restrict__ wgt2,   // [B, N/2]
                     float* __restrict__ out)           // [B*9] R ++ [B*3] t
{
    const int b = blockIdx.x;
    const float4* s4 = src4 + (size_t)b * (NPTS / 2);
    const float4* t4 = tgt4 + (size_t)b * (NPTS / 2);
    const float2* w2 = wgt2 + (size_t)b * (NPTS / 2);

    // acc: 0=sw 1=Sx 2=Sy 3=Tx 4=Ty 5=Pxx 6=Pxy 7=Pyx 8=Pyy  (P_ij = sum w*t_i*s_j)
    float acc[9];
#pragma unroll
    for (int i = 0; i < 9; i++) acc[i] = 0.f;

#pragma unroll 4
    for (int it = 0; it < ITERS; it++) {
        const int n = threadIdx.x + it * THREADS;
        float4 sv = s4[n];
        float4 tv = t4[n];
        float2 ww = w2[n];

        // point 0
        {
            const float w = ww.x;
            const float wtx = w * tv.x, wty = w * tv.y;
            acc[0] += w;
            acc[1] += w * sv.x;
            acc[2] += w * sv.y;
            acc[3] += wtx;
            acc[4] += wty;
            acc[5] += wtx * sv.x;
            acc[6] += wtx * sv.y;
            acc[7] += wty * sv.x;
            acc[8] += wty * sv.y;
        }
        // point 1
        {
            const float w = ww.y;
            const float wtx = w * tv.z, wty = w * tv.w;
            acc[0] += w;
            acc[1] += w * sv.z;
            acc[2] += w * sv.w;
            acc[3] += wtx;
            acc[4] += wty;
            acc[5] += wtx * sv.z;
            acc[6] += wtx * sv.w;
            acc[7] += wty * sv.z;
            acc[8] += wty * sv.w;
        }
    }

    // intra-warp tree reduce (9 scalars)
#pragma unroll
    for (int off = 16; off > 0; off >>= 1)
#pragma unroll
        for (int i = 0; i < 9; i++)
            acc[i] += __shfl_down_sync(0xffffffffu, acc[i], off);

    __shared__ float red[NWARPS][9];
    const int warp = threadIdx.x >> 5;
    const int lane = threadIdx.x & 31;
    if (lane == 0) {
#pragma unroll
        for (int i = 0; i < 9; i++) red[warp][i] = acc[i];
    }
    __syncthreads();

    if (threadIdx.x == 0) {
        float s9[9];
#pragma unroll
        for (int i = 0; i < 9; i++) {
            float v = red[0][i];
#pragma unroll
            for (int wi = 1; wi < NWARPS; wi++) v += red[wi][i];
            s9[i] = v;
        }
        const float sw  = s9[0];
        const float Sx  = s9[1], Sy = s9[2];
        const float Tx  = s9[3], Ty = s9[4];
        const float Pxx = s9[5], Pxy = s9[6], Pyx = s9[7], Pyy = s9[8];

        const float inv = 1.f / (sw + 1e-4f);
        const float scx = Sx * inv, scy = Sy * inv;   // src centroid
        const float tcx = Tx * inv, tcy = Ty * inv;   // tgt centroid

        // Centered cross-covariance (unnormalized; polar factor is scale-invariant)
        const float a  = Pxx - tcx * Sx - scx * Tx + tcx * scx * sw;
        const float bq = Pxy - tcx * Sy - scy * Tx + tcx * scy * sw;
        const float c  = Pyx - tcy * Sx - scx * Ty + tcy * scx * sw;
        const float d  = Pyy - tcy * Sy - scy * Ty + tcy * scy * sw;

        const float det = a * d - bq * c;

        float r00, r01, r10, r11, sgn;
        if (det >= 0.f) {
            const float p = a + d, q = c - bq;             // rotation polar factor
            const float rn = rsqrtf(fmaxf(p * p + q * q, 1e-30f));
            r00 =  p * rn; r01 = -q * rn;
            r10 =  q * rn; r11 =  p * rn;
            sgn = 1.f;
        } else {
            const float p = a - d, q = bq + c;             // reflection polar factor
            const float rn = rsqrtf(fmaxf(p * p + q * q, 1e-30f));
            r00 =  p * rn; r01 =  q * rn;
            r10 =  q * rn; r11 = -p * rn;
            sgn = -1.f;
        }

        float* R = out + (size_t)b * 9;
        R[0] = r00; R[1] = r01; R[2] = 0.f;
        R[3] = r10; R[4] = r11; R[5] = 0.f;
        R[6] = 0.f; R[7] = 0.f; R[8] = sgn;

        // t_src_tgt_intgt = tgt_centroid - R @ src_centroid  (z = 0)
        float* T = out + (size_t)BATCH * 9 + (size_t)b * 3;
        T[0] = tcx - r00 * scx - r01 * scy;
        T[1] = tcy - r10 * scx - r11 * scy;
        T[2] = 0.f;
    }
}

extern "C" void kernel_launch(void* const* d_in, const int* in_sizes, int n_in,
                              void* d_out, int out_size)
{
    const float4* src4 = (const float4*)d_in[0];  // src_coords [B,N,2] f32
    const float4* tgt4 = (const float4*)d_in[1];  // tgt_coords [B,N,2] f32
    const float2* wgt2 = (const float2*)d_in[2];  // weights    [B,1,N] f32
    float* out = (float*)d_out;

    kabsch2d_kernel<<<BATCH, THREADS>>>(src4, tgt4, wgt2, out);
}

// round 3
// speedup vs baseline: 1.0226x; 1.0226x over previous
#include <cuda_runtime.h>

// Weighted 2D Kabsch/Procrustes — closed-form (z-padded 2D covariance has a
// zero third row/col, so R is the embedded 2x2 polar factor; no SVD).
// Pure HBM-bound 9-way weighted reduction over 84MB.

constexpr int BATCH   = 1024;
constexpr int NPTS    = 4096;
constexpr int THREADS = 256;
constexpr int NWARPS  = THREADS / 32;
constexpr int ITERS   = NPTS / 4 / THREADS;   // 4 points per iter -> 4 iters

__global__ __launch_bounds__(THREADS, 7)      // 7 CTAs/SM -> grid 1024 in ONE wave
void kabsch2d_kernel(const float4* __restrict__ src4,   // [B, N/2] (x,y,x,y)
                     const float4* __restrict__ tgt4,
                     const float4* __restrict__ wgt4,   // [B, N/4]
                     float* __restrict__ out)           // [B*9] R ++ [B*3] t
{
    const int b = blockIdx.x;
    const float4* s4 = src4 + (size_t)b * (NPTS / 2);
    const float4* t4 = tgt4 + (size_t)b * (NPTS / 2);
    const float4* w4 = wgt4 + (size_t)b * (NPTS / 4);

    // acc: 0=sw 1=Sx 2=Sy 3=Tx 4=Ty 5=Pxx 6=Pxy 7=Pyx 8=Pyy  (P_ij = sum w*t_i*s_j)
    float acc[9];
#pragma unroll
    for (int i = 0; i < 9; i++) acc[i] = 0.f;

#pragma unroll 2
    for (int it = 0; it < ITERS; it++) {
        const int n = threadIdx.x + it * THREADS;       // quad index (4 points)
        const float4 sv0 = s4[2 * n];
        const float4 sv1 = s4[2 * n + 1];
        const float4 tv0 = t4[2 * n];
        const float4 tv1 = t4[2 * n + 1];
        const float4 wv  = w4[n];

        // point 0: (sv0.x, sv0.y) / (tv0.x, tv0.y) / wv.x
        {
            const float w = wv.x, wtx = w * tv0.x, wty = w * tv0.y;
            acc[0] += w;
            acc[1] += w * sv0.x;  acc[2] += w * sv0.y;
            acc[3] += wtx;        acc[4] += wty;
            acc[5] += wtx * sv0.x; acc[6] += wtx * sv0.y;
            acc[7] += wty * sv0.x; acc[8] += wty * sv0.y;
        }
        // point 1
        {
            const float w = wv.y, wtx = w * tv0.z, wty = w * tv0.w;
            acc[0] += w;
            acc[1] += w * sv0.z;  acc[2] += w * sv0.w;
            acc[3] += wtx;        acc[4] += wty;
            acc[5] += wtx * sv0.z; acc[6] += wtx * sv0.w;
            acc[7] += wty * sv0.z; acc[8] += wty * sv0.w;
        }
        // point 2
        {
            const float w = wv.z, wtx = w * tv1.x, wty = w * tv1.y;
            acc[0] += w;
            acc[1] += w * sv1.x;  acc[2] += w * sv1.y;
            acc[3] += wtx;        acc[4] += wty;
            acc[5] += wtx * sv1.x; acc[6] += wtx * sv1.y;
            acc[7] += wty * sv1.x; acc[8] += wty * sv1.y;
        }
        // point 3
        {
            const float w = wv.w, wtx = w * tv1.z, wty = w * tv1.w;
            acc[0] += w;
            acc[1] += w * sv1.z;  acc[2] += w * sv1.w;
            acc[3] += wtx;        acc[4] += wty;
            acc[5] += wtx * sv1.z; acc[6] += wtx * sv1.w;
            acc[7] += wty * sv1.z; acc[8] += wty * sv1.w;
        }
    }

    // intra-warp tree reduce (9 scalars)
#pragma unroll
    for (int off = 16; off > 0; off >>= 1)
#pragma unroll
        for (int i = 0; i < 9; i++)
            acc[i] += __shfl_down_sync(0xffffffffu, acc[i], off);

    __shared__ float red[NWARPS][9];
    const int warp = threadIdx.x >> 5;
    const int lane = threadIdx.x & 31;
    if (lane == 0) {
#pragma unroll
        for (int i = 0; i < 9; i++) red[warp][i] = acc[i];
    }
    __syncthreads();

    if (threadIdx.x == 0) {
        float s9[9];
#pragma unroll
        for (int i = 0; i < 9; i++) {
            float v = red[0][i];
#pragma unroll
            for (int wi = 1; wi < NWARPS; wi++) v += red[wi][i];
            s9[i] = v;
        }
        const float sw  = s9[0];
        const float Sx  = s9[1], Sy = s9[2];
        const float Tx  = s9[3], Ty = s9[4];
        const float Pxx = s9[5], Pxy = s9[6], Pyx = s9[7], Pyy = s9[8];

        const float inv = 1.f / (sw + 1e-4f);
        const float scx = Sx * inv, scy = Sy * inv;   // src centroid
        const float tcx = Tx * inv, tcy = Ty * inv;   // tgt centroid

        // Centered cross-covariance (unnormalized; polar factor is scale-invariant)
        const float a  = Pxx - tcx * Sx - scx * Tx + tcx * scx * sw;
        const float bq = Pxy - tcx * Sy - scy * Tx + tcx * scy * sw;
        const float c  = Pyx - tcy * Sx - scx * Ty + tcy * scx * sw;
        const float d  = Pyy - tcy * Sy - scy * Ty + tcy * scy * sw;

        const float det = a * d - bq * c;

        float r00, r01, r10, r11, sgn;
        if (det >= 0.f) {
            const float p = a + d, q = c - bq;             // rotation polar factor
            const float rn = rsqrtf(fmaxf(p * p + q * q, 1e-30f));
            r00 =  p * rn; r01 = -q * rn;
            r10 =  q * rn; r11 =  p * rn;
            sgn = 1.f;
        } else {
            const float p = a - d, q = bq + c;             // reflection polar factor
            const float rn = rsqrtf(fmaxf(p * p + q * q, 1e-30f));
            r00 =  p * rn; r01 =  q * rn;
            r10 =  q * rn; r11 = -p * rn;
            sgn = -1.f;
        }

        float* R = out + (size_t)b * 9;
        R[0] = r00; R[1] = r01; R[2] = 0.f;
        R[3] = r10; R[4] = r11; R[5] = 0.f;
        R[6] = 0.f; R[7] = 0.f; R[8] = sgn;

        // t_src_tgt_intgt = tgt_centroid - R @ src_centroid  (z = 0)
        float* T = out + (size_t)BATCH * 9 + (size_t)b * 3;
        T[0] = tcx - r00 * scx - r01 * scy;
        T[1] = tcy - r10 * scx - r11 * scy;
        T[2] = 0.f;
    }
}

extern "C" void kernel_launch(void* const* d_in, const int* in_sizes, int n_in,
                              void* d_out, int out_size)
{
    const float4* src4 = (const float4*)d_in[0];  // src_coords [B,N,2] f32
    const float4* tgt4 = (const float4*)d_in[1];  // tgt_coords [B,N,2] f32
    const float4* wgt4 = (const float4*)d_in[2];  // weights    [B,1,N] f32
    float* out = (float*)d_out;

    kabsch2d_kernel<<<BATCH, THREADS>>>(src4, tgt4, wgt4, out);
}